// round 17
// baseline (speedup 1.0000x reference)
#include <cuda_runtime.h>
#include <cstdint>
#include <math.h>

#define BB 2
#define SS 2048
#define HH 768
#define NHH 12
#define HDD 64
#define WPR 384   // bf16-pair words per 768-row

// Packed global scratch (allocation-free rule: __device__ globals)
__device__ uint32_t g_Xh[4096*WPR],  g_Xl[4096*WPR];
__device__ uint32_t g_WTh[4*HH*WPR], g_WTl[4*HH*WPR];   // [z][n][kpair]
__device__ uint32_t g_Qh[24*SS*32];                     // [bh][s][dpair] fp16x2 (pre-scaled 0.125*log2e)
__device__ uint32_t g_Kh[24*SS*32];                     // [bh][s][dpair] fp16x2
__device__ uint32_t g_Vh[24*64*1024], g_Vl[24*64*1024]; // [bh][d][kvpair] bf16 hi/lo
__device__ uint32_t g_Ch[4096*WPR],  g_Cl[4096*WPR];    // ctx packed bf16 hi/lo

// ---------------------------------------------------------------------------
// Helpers
// ---------------------------------------------------------------------------
__device__ __forceinline__ uint32_t smem_u32(const void* p) {
    uint32_t a;
    asm("{ .reg .u64 t; cvta.to.shared.u64 t, %1; cvt.u32.u64 %0, t; }" : "=r"(a) : "l"(p));
    return a;
}

__device__ __forceinline__ void packbf2(float x0, float x1, uint32_t& hw, uint32_t& lw) {
    uint32_t h;
    asm("cvt.rn.bf16x2.f32 %0, %1, %2;" : "=r"(h) : "f"(x1), "f"(x0));
    float h0 = __uint_as_float(h << 16);
    float h1 = __uint_as_float(h & 0xFFFF0000u);
    asm("cvt.rn.bf16x2.f32 %0, %1, %2;" : "=r"(lw) : "f"(x1 - h1), "f"(x0 - h0));
    hw = h;
}

__device__ __forceinline__ uint32_t packfp2_hi(float x0, float x1) {
    uint32_t h;
    asm("cvt.rn.f16x2.f32 %0, %1, %2;" : "=r"(h) : "f"(x1), "f"(x0));
    return h;
}

__device__ __forceinline__ void mmabf2(float d[4], const uint32_t a[4], uint32_t b0, uint32_t b1) {
    asm volatile(
        "mma.sync.aligned.m16n8k16.row.col.f32.bf16.bf16.f32 "
        "{%0,%1,%2,%3}, {%4,%5,%6,%7}, {%8,%9}, {%0,%1,%2,%3};"
        : "+f"(d[0]), "+f"(d[1]), "+f"(d[2]), "+f"(d[3])
        : "r"(a[0]), "r"(a[1]), "r"(a[2]), "r"(a[3]), "r"(b0), "r"(b1));
}

__device__ __forceinline__ void mmafp2(float d[4], const uint32_t a[4], uint32_t b0, uint32_t b1) {
    asm volatile(
        "mma.sync.aligned.m16n8k16.row.col.f32.f16.f16.f32 "
        "{%0,%1,%2,%3}, {%4,%5,%6,%7}, {%8,%9}, {%0,%1,%2,%3};"
        : "+f"(d[0]), "+f"(d[1]), "+f"(d[2]), "+f"(d[3])
        : "r"(a[0]), "r"(a[1]), "r"(a[2]), "r"(a[3]), "r"(b0), "r"(b1));
}

__device__ __forceinline__ void ldsm4(uint32_t r[4], uint32_t addr) {
    asm volatile("ldmatrix.sync.aligned.m8n8.x4.shared.b16 {%0,%1,%2,%3}, [%4];"
        : "=r"(r[0]), "=r"(r[1]), "=r"(r[2]), "=r"(r[3]) : "r"(addr));
}

__device__ __forceinline__ void cpa16(uint32_t saddr, const void* g) {
    asm volatile("cp.async.cg.shared.global [%0], [%1], 16;" :: "r"(saddr), "l"(g));
}
#define CPA_COMMIT() asm volatile("cp.async.commit_group;" ::: "memory")
#define CPA_WAIT1()  asm volatile("cp.async.wait_group 1;" ::: "memory")
#define CPA_WAIT0()  asm volatile("cp.async.wait_group 0;" ::: "memory")

// 2^x via MUFU. Scores pre-scaled by log2(e) upstream; masked ~-14427 -> 0.
__device__ __forceinline__ float fex2(float x) {
    float r;
    asm("ex2.approx.f32 %0, %1;" : "=f"(r) : "f"(x));
    return r;
}

// ---------------------------------------------------------------------------
// Prep kernels
// ---------------------------------------------------------------------------
__global__ void pack_x(const float* __restrict__ X) {
    int i = blockIdx.x * 256 + threadIdx.x;
    const int n = 4096 * WPR;
    for (int w = i; w < n; w += gridDim.x * 256) {
        float2 v = ((const float2*)X)[w];
        packbf2(v.x, v.y, g_Xh[w], g_Xl[w]);
    }
}

__global__ void transpose_pack_w(const float* __restrict__ W0, const float* __restrict__ W1,
                                 const float* __restrict__ W2, const float* __restrict__ W3) {
    __shared__ float t[32][33];
    int z = blockIdx.z;
    const float* W = z == 0 ? W0 : z == 1 ? W1 : z == 2 ? W2 : W3;
    uint32_t* WTh = g_WTh + (size_t)z * HH * WPR;
    uint32_t* WTl = g_WTl + (size_t)z * HH * WPR;
    int bx = blockIdx.x * 32, by = blockIdx.y * 32;
    int tx = threadIdx.x, ty = threadIdx.y;
    #pragma unroll
    for (int i = 0; i < 4; i++)
        t[ty + 8*i][tx] = W[(size_t)(by + ty + 8*i) * HH + bx + tx];
    __syncthreads();
    int li = ty * 32 + tx;
    #pragma unroll
    for (int it = 0; it < 2; it++) {
        int q = li + it * 256;
        int n_l = q >> 4, w = q & 15;
        uint32_t hw, lw;
        packbf2(t[2*w][n_l], t[2*w + 1][n_l], hw, lw);
        size_t addr = (size_t)(bx + n_l) * WPR + (by >> 1) + w;
        WTh[addr] = hw; WTl[addr] = lw;
    }
}

// ---------------------------------------------------------------------------
// Projection GEMM (2xBF16 m16n8k16), cp.async double-buffered.
// ---------------------------------------------------------------------------
#define W_BIAS 15360
#define W_COS  15424
#define W_SIN  15488
#define GEMM_SMEM (15552*4)

__device__ __forceinline__ void gemm_stage(const uint32_t* __restrict__ Ahg,
                                           const uint32_t* __restrict__ Alg,
                                           const uint32_t* __restrict__ Bhg,
                                           const uint32_t* __restrict__ Blg,
                                           int m0, int n0, int k0w, int buf,
                                           uint32_t sb, int tid) {
    const int r4 = tid >> 2, u4 = tid & 3;
    const uint32_t ab = buf*5120, bb = 10240 + buf*2560;
    #pragma unroll
    for (int it = 0; it < 2; it++) {
        int r = r4 + it*64;
        uint32_t wo = (uint32_t)(r*20 + u4*4);
        cpa16(sb + (ab + wo)*4,        Ahg + (size_t)(m0 + r)*WPR + k0w + u4*4);
        cpa16(sb + (ab + 2560 + wo)*4, Alg + (size_t)(m0 + r)*WPR + k0w + u4*4);
    }
    {
        uint32_t wo = (uint32_t)(r4*20 + u4*4);
        cpa16(sb + (bb + wo)*4,        Bhg + (size_t)(n0 + r4)*WPR + k0w + u4*4);
        cpa16(sb + (bb + 1280 + wo)*4, Blg + (size_t)(n0 + r4)*WPR + k0w + u4*4);
    }
}

__device__ __forceinline__ void gemm_main(const uint32_t* __restrict__ Ahg,
                                          const uint32_t* __restrict__ Alg,
                                          const uint32_t* __restrict__ Bhg,
                                          const uint32_t* __restrict__ Blg,
                                          int m0, int n0, uint32_t* smw,
                                          float acc[2][4][4]) {
    const int tid = threadIdx.x;
    const int wid = tid >> 5, lane = tid & 31;
    const int wm = wid >> 1, wn = wid & 1;
    const uint32_t sb = smem_u32(smw);

    const int l8 = (lane >> 3) & 1, l16 = lane >> 4, l7 = lane & 7;
    const int aoff0 = (wm*32 +        l8*8 + l7)*20 + l16*4;
    const int aoff1 = aoff0 + 16*20;
    const int boff0 = (wn*32 +        l16*8 + l7)*20 + l8*4;
    const int boff1 = boff0 + 16*20;

    gemm_stage(Ahg, Alg, Bhg, Blg, m0, n0, 0, 0, sb, tid);
    CPA_COMMIT();

    for (int kb = 0; kb < 24; kb++) {
        const int cur = kb & 1;
        __syncthreads();
        if (kb < 23)
            gemm_stage(Ahg, Alg, Bhg, Blg, m0, n0, (kb + 1)*16, 1 - cur, sb, tid);
        CPA_COMMIT();
        if (kb < 23) CPA_WAIT1(); else CPA_WAIT0();
        __syncthreads();

        const int AH = cur*5120, AL = AH + 2560;
        const int BH = 10240 + cur*2560, BL = BH + 1280;
        #pragma unroll
        for (int ks = 0; ks < 2; ks++) {
            int kk = ks * 8;
            uint32_t ah0[4], ah1[4], al0[4], al1[4];
            uint32_t bh0[4], bh1[4], bl0[4], bl1[4];
            ldsm4(ah0, sb + (AH + aoff0 + kk)*4);
            ldsm4(ah1, sb + (AH + aoff1 + kk)*4);
            ldsm4(al0, sb + (AL + aoff0 + kk)*4);
            ldsm4(al1, sb + (AL + aoff1 + kk)*4);
            ldsm4(bh0, sb + (BH + boff0 + kk)*4);
            ldsm4(bh1, sb + (BH + boff1 + kk)*4);
            ldsm4(bl0, sb + (BL + boff0 + kk)*4);
            ldsm4(bl1, sb + (BL + boff1 + kk)*4);
            mmabf2(acc[0][0], al0, bh0[0], bh0[1]); mmabf2(acc[0][1], al0, bh0[2], bh0[3]);
            mmabf2(acc[0][2], al0, bh1[0], bh1[1]); mmabf2(acc[0][3], al0, bh1[2], bh1[3]);
            mmabf2(acc[1][0], al1, bh0[0], bh0[1]); mmabf2(acc[1][1], al1, bh0[2], bh0[3]);
            mmabf2(acc[1][2], al1, bh1[0], bh1[1]); mmabf2(acc[1][3], al1, bh1[2], bh1[3]);
            mmabf2(acc[0][0], ah0, bl0[0], bl0[1]); mmabf2(acc[0][1], ah0, bl0[2], bl0[3]);
            mmabf2(acc[0][2], ah0, bl1[0], bl1[1]); mmabf2(acc[0][3], ah0, bl1[2], bl1[3]);
            mmabf2(acc[1][0], ah1, bl0[0], bl0[1]); mmabf2(acc[1][1], ah1, bl0[2], bl0[3]);
            mmabf2(acc[1][2], ah1, bl1[0], bl1[1]); mmabf2(acc[1][3], ah1, bl1[2], bl1[3]);
            mmabf2(acc[0][0], ah0, bh0[0], bh0[1]); mmabf2(acc[0][1], ah0, bh0[2], bh0[3]);
            mmabf2(acc[0][2], ah0, bh1[0], bh1[1]); mmabf2(acc[0][3], ah0, bh1[2], bh1[3]);
            mmabf2(acc[1][0], ah1, bh0[0], bh0[1]); mmabf2(acc[1][1], ah1, bh0[2], bh0[3]);
            mmabf2(acc[1][2], ah1, bh1[0], bh1[1]); mmabf2(acc[1][3], ah1, bh1[2], bh1[3]);
        }
    }
    __syncthreads();
}

__device__ __forceinline__ void stage_acc(uint32_t* smw, float acc[2][4][4]) {
    const int tid = threadIdx.x;
    const int wid = tid >> 5, lane = tid & 31, g = lane >> 2, c = lane & 3;
    const int wm = wid >> 1, wn = wid & 1;
    float* Sg = (float*)smw;
    #pragma unroll
    for (int mt = 0; mt < 2; mt++) {
        int r0 = wm*32 + mt*16 + g;
        #pragma unroll
        for (int nt = 0; nt < 4; nt++) {
            int col = wn*32 + nt*8 + 2*c;
            *(float2*)&Sg[r0*66 + col]       = make_float2(acc[mt][nt][0], acc[mt][nt][1]);
            *(float2*)&Sg[(r0 + 8)*66 + col] = make_float2(acc[mt][nt][2], acc[mt][nt][3]);
        }
    }
    __syncthreads();
}

// ---------------------------------------------------------------------------
// QKV projection + bias + RoPE (head-indexed, faithful), packed outputs.
// ---------------------------------------------------------------------------
__global__ __launch_bounds__(256, 2)
void qkv_pk(const float* __restrict__ bq, const float* __restrict__ bk,
            const float* __restrict__ bv,
            const float* __restrict__ cosp, const float* __restrict__ sinp) {
    extern __shared__ uint32_t smw[];
    int tid = threadIdx.x;
    int z = blockIdx.z;
    int m0 = blockIdx.y * 128, n0 = blockIdx.x * 64;
    const float* bias = z == 0 ? bq : z == 1 ? bk : bv;

    if (tid < 64) {
        ((float*)(smw + W_BIAS))[tid] = bias[n0 + tid];
        ((float*)(smw + W_COS ))[tid] = cosp[n0 + tid];
        ((float*)(smw + W_SIN ))[tid] = sinp[n0 + tid];
    }
    __syncthreads();
    float acc[2][4][4] = {};
    size_t zo = (size_t)z * HH * WPR;
    gemm_main(g_Xh, g_Xl, g_WTh + zo, g_WTl + zo, m0, n0, smw, acc);
    stage_acc(smw, acc);

    float* Sg = (float*)smw;
    const float* sBias = (const float*)(smw + W_BIAS);
    const float* sCos  = (const float*)(smw + W_COS);
    const float* sSin  = (const float*)(smw + W_SIN);
    int m = tid >> 1;
    int half = (tid & 1) * 32;
    int mg = m0 + m;
    int bbt = mg >> 11, s = mg & 2047;
    int h = blockIdx.x;
    int bh = bbt * NHH + h;

    float o[32];
    if (z < 2) {
        float qsc = (z == 0) ? 0.18033688011112042f : 1.0f;
        #pragma unroll
        for (int i = 0; i < 32; i++) {
            int cg = half + i;
            float v = Sg[m*66 + cg] + sBias[cg];
            int pc = (cg < 32) ? (2*cg + 1) : (2*(cg - 32));
            float pv = Sg[m*66 + pc] + sBias[pc];
            float sgn = (cg < 32) ? -1.0f : 1.0f;
            o[i] = (v * sCos[cg] + sgn * pv * sSin[cg]) * qsc;
        }
        uint32_t* Dh = (z == 0 ? g_Qh : g_Kh) + ((size_t)bh * SS + s) * 32 + (tid & 1) * 16;
        #pragma unroll
        for (int j = 0; j < 16; j++)
            Dh[j] = packfp2_hi(o[2*j], o[2*j + 1]);
    } else {
        #pragma unroll
        for (int i = 0; i < 32; i++)
            o[i] = Sg[m*66 + half + i] + sBias[half + i];
        size_t base = (size_t)bh * 64 * 1024 + ((m0 & 2047) >> 1) + (tid >> 2);
        #pragma unroll
        for (int i = 0; i < 32; i++) {
            float pv = __shfl_down_sync(0xFFFFFFFFu, o[i], 2);
            if (!(tid & 2)) {
                uint32_t hw, lw;
                packbf2(o[i], pv, hw, lw);
                g_Vh[base + (size_t)(half + i) * 1024] = hw;
                g_Vl[base + (size_t)(half + i) * 1024] = lw;
            }
        }
    }
}

__global__ __launch_bounds__(256, 2)
void o_pk(const float* __restrict__ bo, float* __restrict__ out) {
    extern __shared__ uint32_t smw[];
    int tid = threadIdx.x;
    int m0 = blockIdx.y * 128, n0 = blockIdx.x * 64;
    if (tid < 64) ((float*)(smw + W_BIAS))[tid] = bo[n0 + tid];
    __syncthreads();

    float acc[2][4][4] = {};
    size_t zo = (size_t)3 * HH * WPR;
    gemm_main(g_Ch, g_Cl, g_WTh + zo, g_WTl + zo, m0, n0, smw, acc);
    stage_acc(smw, acc);

    float* Sg = (float*)smw;
    const float* sBias = (const float*)(smw + W_BIAS);
    int m = tid >> 1;
    int half = (tid & 1) * 32;
    float* dst = out + (size_t)(m0 + m) * HH + n0 + half;
    #pragma unroll
    for (int i4 = 0; i4 < 8; i4++) {
        float4 v;
        v.x = Sg[m*66 + half + i4*4 + 0] + sBias[half + i4*4 + 0];
        v.y = Sg[m*66 + half + i4*4 + 1] + sBias[half + i4*4 + 1];
        v.z = Sg[m*66 + half + i4*4 + 2] + sBias[half + i4*4 + 2];
        v.w = Sg[m*66 + half + i4*4 + 3] + sBias[half + i4*4 + 3];
        *(float4*)(dst + i4*4) = v;
    }
}

// ---------------------------------------------------------------------------
// Flash attention v9b: cross-tile software pipeline (QK(jt+1) issued before
// PV(jt) so 96 independent PV mma cover the QK->softmax latency). Packed P
// in smem. FIXED LAYOUT (R16 bug): P hi/lo need 4608 words EACH (128 rows x
// 36); R16 allocated 2304 -> OOB writes past the smem allocation.
// smem words: K bufs 2x2304 @0; V bufs 3x4608 @4608 (hi+0, lo+2304);
// Q @18432 (4608); P hi @23040 (4608); P lo @27648 (4608);
// masks 3x64 @32256. Total 32448 w = 129.8 KB -> 1 CTA/SM.
// ---------------------------------------------------------------------------
#define FK_BUF(q)  ((q)*2304)
#define FV_BUFH(q) (4608 + (q)*4608)
#define FQ_OFF 18432
#define FP_H   23040
#define FP_L   27648
#define FMSK(q) (32256 + (q)*64)
#define FLASH_SMEM (32448*4)

__global__ __launch_bounds__(256, 1)
void flash_pk(const float* __restrict__ mask) {
    extern __shared__ uint32_t smw[];
    const uint32_t sb = smem_u32(smw);
    int bh = blockIdx.y;
    int b = bh / NHH, h = bh % NHH;
    int sq0 = blockIdx.x * 128;
    const float* mkg = mask + (size_t)b * SS;
    int tid = threadIdx.x;
    int wid = tid >> 5, lane = tid & 31, g = lane >> 2, c = lane & 3;
    const int l8 = (lane >> 3) & 1, l16 = lane >> 4, l7 = lane & 7;

    const uint32_t* Khg0 = g_Kh + (size_t)bh * SS * 32;
    const uint32_t* Vhg0 = g_Vh + (size_t)bh * 64 * 1024;
    const uint32_t* Vlg0 = g_Vl + (size_t)bh * 64 * 1024;
    const int cr = tid >> 3, cu = tid & 7;   // staging row/quad

    const int qoff = (wid*16 + l8*8 + l7)*36 + l16*4;   // A-frag (Q and P)
    int koff[4];
    #pragma unroll
    for (int t = 0; t < 4; t++)
        koff[t] = (t*16 + l16*8 + l7)*36 + l8*4;        // B-frag (K and V)

    #define STAGE_KV(jn) do { \
        uint32_t kbo = FK_BUF((jn) & 1); \
        uint32_t vho = FV_BUFH((jn) % 3); \
        const uint32_t* Khg = Khg0 + (size_t)(jn)*64*32 + cr*32 + cu*4; \
        const uint32_t* Vhg = Vhg0 + (jn)*32 + (size_t)cr*1024 + cu*4; \
        const uint32_t* Vlg = Vlg0 + (jn)*32 + (size_t)cr*1024 + cu*4; \
        _Pragma("unroll") \
        for (int it_ = 0; it_ < 2; it_++) { \
            int r_ = cr + it_*32; \
            uint32_t wo_ = (r_*36 + cu*4)*4; \
            cpa16(sb + kbo*4          + wo_, Khg + it_*32*32); \
            cpa16(sb + vho*4          + wo_, Vhg + (size_t)it_*32*1024); \
            cpa16(sb + (vho + 2304)*4 + wo_, Vlg + (size_t)it_*32*1024); \
        } \
        if (tid < 16) cpa16(sb + (FMSK((jn) % 3) + tid*4)*4, mkg + (jn)*64 + tid*4); \
    } while (0)

    // prologue: stage tiles 0 and 1 (two commit groups), stage Q, wait tile 0
    STAGE_KV(0);
    CPA_COMMIT();
    STAGE_KV(1);
    CPA_COMMIT();
    {
        const uint32_t* Qhg = g_Qh + ((size_t)bh * SS + sq0) * 32;
        #pragma unroll
        for (int it = 0; it < 4; it++) {
            int idx = tid + it * 256;
            int r = idx >> 3, u = idx & 7;
            *(uint4*)(smw + FQ_OFF + r*36 + u*4) = *(const uint4*)(Qhg + r*32 + u*4);
        }
    }
    CPA_WAIT1();       // tile 0 arrived (tile 1 may be in flight)
    __syncthreads();   // tile 0 + Q visible

    float oa[8][4] = {};
    float l0r = 0.0f, l1r = 0.0f;
    float sv[8][4];

    // QK(0) + softmax(0)
    {
        #pragma unroll
        for (int nt = 0; nt < 8; nt++)
            #pragma unroll
            for (int e = 0; e < 4; e++) sv[nt][e] = 0.0f;
        #pragma unroll
        for (int ks = 0; ks < 4; ks++) {
            int kk = ks * 8;
            uint32_t qh[4];
            ldsm4(qh, sb + (FQ_OFF + qoff + kk)*4);
            #pragma unroll
            for (int t = 0; t < 4; t++) {
                uint32_t bhf[4];
                ldsm4(bhf, sb + (FK_BUF(0) + koff[t] + kk)*4);
                mmafp2(sv[2*t],   qh, bhf[0], bhf[1]);
                mmafp2(sv[2*t+1], qh, bhf[2], bhf[3]);
            }
        }
        const float* msf = (const float*)(smw + FMSK(0));
        #pragma unroll
        for (int nt = 0; nt < 8; nt++) {
            int col = nt*8 + 2*c;
            float ma = fmaf(msf[col],     14426.950408889634f, -14426.950408889634f);
            float mb = fmaf(msf[col + 1], 14426.950408889634f, -14426.950408889634f);
            sv[nt][0] = fex2(sv[nt][0] + ma); l0r += sv[nt][0];
            sv[nt][1] = fex2(sv[nt][1] + mb); l0r += sv[nt][1];
            sv[nt][2] = fex2(sv[nt][2] + ma); l1r += sv[nt][2];
            sv[nt][3] = fex2(sv[nt][3] + mb); l1r += sv[nt][3];
        }
    }

    for (int jt = 0; jt < 32; jt++) {
        __syncthreads();   // all reads of buffers to be overwritten are done

        // pack sv(jt) -> warp-private P smem (conflict-free STS)
        {
            int rA = (wid*16 + g)*36, rB = (wid*16 + g + 8)*36;
            #pragma unroll
            for (int nt = 0; nt < 8; nt++) {
                uint32_t hw, lw;
                packbf2(sv[nt][0], sv[nt][1], hw, lw);
                smw[FP_H + rA + nt*4 + c] = hw;
                smw[FP_L + rA + nt*4 + c] = lw;
                packbf2(sv[nt][2], sv[nt][3], hw, lw);
                smw[FP_H + rB + nt*4 + c] = hw;
                smw[FP_L + rB + nt*4 + c] = lw;
            }
        }

        if (jt < 30) {
            STAGE_KV(jt + 2);
            CPA_COMMIT();
            CPA_WAIT1();            // tile jt+1 arrived
        } else if (jt == 30) {
            CPA_WAIT0();            // tile 31 arrived
        }
        __syncthreads();            // tile jt+1 data + P visible

        // --- QK(jt+1) first: its latency is covered by PV(jt)'s 96 mma ---
        if (jt < 31) {
            #pragma unroll
            for (int nt = 0; nt < 8; nt++)
                #pragma unroll
                for (int e = 0; e < 4; e++) sv[nt][e] = 0.0f;
            uint32_t kbo = FK_BUF((jt + 1) & 1);
            #pragma unroll
            for (int ks = 0; ks < 4; ks++) {
                int kk = ks * 8;
                uint32_t qh[4];
                ldsm4(qh, sb + (FQ_OFF + qoff + kk)*4);
                #pragma unroll
                for (int t = 0; t < 4; t++) {
                    uint32_t bhf[4];
                    ldsm4(bhf, sb + (kbo + koff[t] + kk)*4);
                    mmafp2(sv[2*t],   qh, bhf[0], bhf[1]);
                    mmafp2(sv[2*t+1], qh, bhf[2], bhf[3]);
                }
            }
        }

        // --- PV(jt): P from smem (ldmatrix), V buf jt%3, 3-pass bf16 ---
        {
            uint32_t vho = FV_BUFH(jt % 3);
            #pragma unroll
            for (int ks = 0; ks < 4; ks++) {
                int kk = ks * 8;
                uint32_t pah[4], pal[4];
                ldsm4(pah, sb + (FP_H + qoff + kk)*4);
                ldsm4(pal, sb + (FP_L + qoff + kk)*4);
                #pragma unroll
                for (int t = 0; t < 4; t++) {
                    uint32_t vh[4], vl[4];
                    ldsm4(vh, sb + (vho +        koff[t] + kk)*4);
                    ldsm4(vl, sb + (vho + 2304 + koff[t] + kk)*4);
                    mmabf2(oa[2*t],   pal, vh[0], vh[1]);
                    mmabf2(oa[2*t+1], pal, vh[2], vh[3]);
                    mmabf2(oa[2*t],   pah, vl[0], vl[1]);
                    mmabf2(oa[2*t+1], pah, vl[2], vl[3]);
                    mmabf2(oa[2*t],   pah, vh[0], vh[1]);
                    mmabf2(oa[2*t+1], pah, vh[2], vh[3]);
                }
            }
        }

        // --- softmax(jt+1): QK results long ready (PV mma in between) ---
        if (jt < 31) {
            const float* msf = (const float*)(smw + FMSK((jt + 1) % 3));
            #pragma unroll
            for (int nt = 0; nt < 8; nt++) {
                int col = nt*8 + 2*c;
                float ma = fmaf(msf[col],     14426.950408889634f, -14426.950408889634f);
                float mb = fmaf(msf[col + 1], 14426.950408889634f, -14426.950408889634f);
                sv[nt][0] = fex2(sv[nt][0] + ma); l0r += sv[nt][0];
                sv[nt][1] = fex2(sv[nt][1] + mb); l0r += sv[nt][1];
                sv[nt][2] = fex2(sv[nt][2] + ma); l1r += sv[nt][2];
                sv[nt][3] = fex2(sv[nt][3] + mb); l1r += sv[nt][3];
            }
        }
    }

    // --- close lane sums, normalize, write ctx packed ---
    l0r += __shfl_xor_sync(0xFFFFFFFFu, l0r, 1);
    l0r += __shfl_xor_sync(0xFFFFFFFFu, l0r, 2);
    l1r += __shfl_xor_sync(0xFFFFFFFFu, l1r, 1);
    l1r += __shfl_xor_sync(0xFFFFFFFFu, l1r, 2);
    float inv0 = 1.0f / l0r, inv1 = 1.0f / l1r;
    int sA = sq0 + wid*16 + g, sB = sA + 8;
    size_t baseA = ((size_t)(b*SS + sA)) * WPR + h*32;
    size_t baseB = ((size_t)(b*SS + sB)) * WPR + h*32;
    #pragma unroll
    for (int nch = 0; nch < 8; nch++) {
        uint32_t hw, lw;
        packbf2(oa[nch][0] * inv0, oa[nch][1] * inv0, hw, lw);
        g_Ch[baseA + nch*4 + c] = hw; g_Cl[baseA + nch*4 + c] = lw;
        packbf2(oa[nch][2] * inv1, oa[nch][3] * inv1, hw, lw);
        g_Ch[baseB + nch*4 + c] = hw; g_Cl[baseB + nch*4 + c] = lw;
    }
    #undef STAGE_KV
}

extern "C" void kernel_launch(void* const* d_in, const int* in_sizes, int n_in,
                              void* d_out, int out_size) {
    const float* hs   = (const float*)d_in[0];
    const float* mask = (const float*)d_in[1];
    const float* Wq   = (const float*)d_in[2];
    const float* bq   = (const float*)d_in[3];
    const float* Wk   = (const float*)d_in[4];
    const float* bk   = (const float*)d_in[5];
    const float* Wv   = (const float*)d_in[6];
    const float* bv   = (const float*)d_in[7];
    const float* Wo   = (const float*)d_in[8];
    const float* bo   = (const float*)d_in[9];
    const float* cosp = (const float*)d_in[10];
    const float* sinp = (const float*)d_in[11];
    float* out = (float*)d_out;

    cudaFuncSetAttribute(qkv_pk,   cudaFuncAttributeMaxDynamicSharedMemorySize, GEMM_SMEM);
    cudaFuncSetAttribute(o_pk,     cudaFuncAttributeMaxDynamicSharedMemorySize, GEMM_SMEM);
    cudaFuncSetAttribute(flash_pk, cudaFuncAttributeMaxDynamicSharedMemorySize, FLASH_SMEM);

    pack_x<<<768, 256>>>(hs);
    transpose_pack_w<<<dim3(24, 24, 4), dim3(32, 8)>>>(Wq, Wk, Wv, Wo);
    qkv_pk<<<dim3(12, 32, 3), 256, GEMM_SMEM>>>(bq, bk, bv, cosp, sinp);
    flash_pk<<<dim3(16, 24), 256, FLASH_SMEM>>>(mask);
    o_pk<<<dim3(12, 32), 256, GEMM_SMEM>>>(bo, out);
}